// round 7
// baseline (speedup 1.0000x reference)
#include <cuda_runtime.h>

// Problem constants (fixed by the reference)
#define DD   41
#define HH   159
#define WW   159
#define CIN  32
#define COUT 64
#define NB   2
#define NPTS 150000
#define DM   20
#define HM   79
#define WM   79
#define WSZ  (27 * CIN * COUT)                  // 55296 floats per weight tensor
#define MIDSZ (NB * DM * HM * WM * COUT)        // 15,976,960 floats
#define OUTSZ ((long)NB * CIN * DD * HH * WW)   // 66,337,344 floats

#define NW 16     // warps per CTA (scatter)
#define NWG 12    // warps per CTA (gather)
#define GP 8      // points per group (all same parity class)

// Scratch (device globals — zero-initialized at load; counters self-reset per replay)
__device__ alignas(16) float g_mid[MIDSZ];
__device__ int g_order[NPTS];
__device__ int g_cnt[8];      // live histogram (reset by scan for next replay)
__device__ int g_cntS[8];     // stable copy used by conv kernels
__device__ int g_bstart[8];
__device__ int g_ng[8];       // groups of GP per class
__device__ int g_cursor[8];   // scatter_idx cursors
__device__ int g_ccur1[8];    // scatter_conv chunk cursors
__device__ int g_ccur2[8];    // gather_deconv chunk cursors

// Packed fp32x2 FMA (sm_103a FFMA2 — PTX-only path, 2x fp32 rate)
__device__ __forceinline__ void ffma2(unsigned long long& d,
                                      unsigned long long a,
                                      unsigned long long b) {
    asm("fma.rn.f32x2 %0, %1, %2, %0;" : "+l"(d) : "l"(a), "l"(b));
}

// ---------------------------------------------------------------------------
// Kernel 0: zero d_out + g_mid, and build the parity histogram (fused)
// ---------------------------------------------------------------------------
__global__ void zero_hist(float4* __restrict__ out, const int* __restrict__ coors) {
    __shared__ int h[8];
    if (threadIdx.x < 8) h[threadIdx.x] = 0;
    __syncthreads();

    const long n_out4 = OUTSZ / 4;
    const long n_mid4 = MIDSZ / 4;
    const long total  = n_out4 + n_mid4;
    float4* mid4 = reinterpret_cast<float4*>(g_mid);
    const float4 z = make_float4(0.f, 0.f, 0.f, 0.f);
    const long gstride = (long)gridDim.x * blockDim.x;
    for (long i = blockIdx.x * (long)blockDim.x + threadIdx.x; i < total; i += gstride) {
        if (i < n_out4) out[i] = z;
        else            mid4[i - n_out4] = z;
    }

    const int4* c4 = reinterpret_cast<const int4*>(coors);
    for (int n = blockIdx.x * blockDim.x + threadIdx.x; n < NPTS; n += (int)gstride) {
        const int4 c = c4[n];
        atomicAdd(&h[((c.y & 1) << 2) | ((c.z & 1) << 1) | (c.w & 1)], 1);
    }
    __syncthreads();
    if (threadIdx.x < 8 && h[threadIdx.x]) atomicAdd(&g_cnt[threadIdx.x], h[threadIdx.x]);
}

// ---------------------------------------------------------------------------
// Scan: prefix sums, cursors, and counter self-reset for graph replay
// ---------------------------------------------------------------------------
__global__ void scan_kernel() {
    int s = 0;
    for (int b = 0; b < 8; b++) {
        const int c = g_cnt[b];
        g_cntS[b]   = c;
        g_bstart[b] = s;
        g_cursor[b] = s;
        g_ng[b]     = (c + GP - 1) / GP;
        g_ccur1[b]  = 0;
        g_ccur2[b]  = 0;
        g_cnt[b]    = 0;      // reset for next replay
        s += c;
    }
}

__global__ void scatter_idx_kernel(const int* __restrict__ coors) {
    const int n = blockIdx.x * blockDim.x + threadIdx.x;
    if (n >= NPTS) return;
    const int4 c  = reinterpret_cast<const int4*>(coors)[n];
    const int cls = ((c.y & 1) << 2) | ((c.z & 1) << 1) | (c.w & 1);
    const int lane = threadIdx.x & 31;
    unsigned mm = __match_any_sync(__activemask(), cls);
    int leader = __ffs(mm) - 1;
    int rank   = __popc(mm & ((1u << lane) - 1));
    int base;
    if (lane == leader) base = atomicAdd(&g_cursor[cls], __popc(mm));
    base = __shfl_sync(mm, base, leader);
    g_order[base + rank] = n;
}

// ---------------------------------------------------------------------------
// Phase 1: scatter conv. Persistent CTAs, class-major chunk scheduling.
// Per class only its <=8 taps live in smem (64KB) -> 2 CTAs/SM.
// Warp handles GP=8 same-parity points; lane = (half h, co-quad q).
// ---------------------------------------------------------------------------
__global__ void __launch_bounds__(512, 2) scatter_conv(
    const float* __restrict__ feats,
    const int*   __restrict__ coors,
    const float* __restrict__ w1) {
    extern __shared__ float sh[];
    float4* ws4 = reinterpret_cast<float4*>(sh);                       // 8*512 float4
    unsigned long long* fd = reinterpret_cast<unsigned long long*>(sh + 16384); // NW*GP*32 ull
    int4* sco = reinterpret_cast<int4*>(fd + NW * GP * 32);            // NW*GP int4
    __shared__ int s_chunk;

    const int tid  = threadIdx.x;
    const int warp = tid >> 5, lane = tid & 31;
    const int h = lane >> 4, q = lane & 15;
    unsigned long long* fdw = fd + warp * (GP * 32);
    int4* scow = sco + warp * GP;
    const int4* c4 = reinterpret_cast<const int4*>(coors);

    int loaded = -1;
    for (int b = 0; b < 8; b++) {
        const int zo = (b >> 2) & 1, yo = (b >> 1) & 1, xo = b & 1;
        const int nx = 2 - xo, ny = 2 - yo, nz = 2 - zo;
        const int ntap = nx * ny * nz;
        const int ng = g_ng[b];
        const int bs = g_bstart[b], bc = g_cntS[b];
        while (true) {
            __syncthreads();
            if (tid == 0) s_chunk = atomicAdd(&g_ccur1[b], NW);
            __syncthreads();
            const int ch = s_chunk;
            if (ch >= ng) break;
            if (loaded != b) {
                for (int i = tid; i < ntap * 512; i += blockDim.x) {
                    const int it = i >> 9, r = i & 511;
                    const int ix = it % nx, iy = (it / nx) % ny, iz = it / (nx * ny);
                    const int kz = zo ? 1 : (iz ? 2 : 0);
                    const int ky = yo ? 1 : (iy ? 2 : 0);
                    const int kx = xo ? 1 : (ix ? 2 : 0);
                    ws4[i] = reinterpret_cast<const float4*>(w1)[((kz * 3 + ky) * 3 + kx) * 512 + r];
                }
                __syncthreads();
                loaded = b;
            }
            const int gi = ch + warp;
            if (gi >= ng) continue;
            const int base = bs + gi * GP;
            const int cnt  = min(GP, bs + bc - base);

            int idj = 0;
            if (lane < GP) {
                idj = g_order[base + ((lane < cnt) ? lane : 0)];
                scow[lane] = __ldg(c4 + idj);
            }
            __syncwarp();
            #pragma unroll
            for (int j = 0; j < GP; j++) {
                const int id = __shfl_sync(0xffffffffu, idj, j);
                const float v = (j < cnt) ? feats[id * CIN + lane] : 0.f;
                unsigned long long p = (unsigned long long)__float_as_uint(v);
                fdw[j * 32 + lane] = p | (p << 32);
            }
            __syncwarp();

            for (int it = 0; it < ntap; it++) {
                const int ix = it % nx, iy = (it / nx) % ny, iz = it / (nx * ny);
                const float4* wt = ws4 + it * 512;
                unsigned long long acc[4][2] = {{0,0},{0,0},{0,0},{0,0}};
                #pragma unroll
                for (int cb = 0; cb < 16; cb++) {
                    const ulonglong2 wA = *reinterpret_cast<const ulonglong2*>(wt + (2 * cb) * 16 + q);
                    const ulonglong2 wB = *reinterpret_cast<const ulonglong2*>(wt + (2 * cb + 1) * 16 + q);
                    #pragma unroll
                    for (int i = 0; i < 4; i++) {
                        const ulonglong2 f = *reinterpret_cast<const ulonglong2*>(fdw + (h + 2 * i) * 32 + 2 * cb);
                        ffma2(acc[i][0], f.x, wA.x); ffma2(acc[i][1], f.x, wA.y);
                        ffma2(acc[i][0], f.y, wB.x); ffma2(acc[i][1], f.y, wB.y);
                    }
                }
                #pragma unroll
                for (int i = 0; i < 4; i++) {
                    const int j = h + 2 * i;
                    if (j < cnt) {
                        const int4 c = scow[j];
                        const int mz = (c.y >> 1) - iz;
                        const int my = (c.z >> 1) - iy;
                        const int mx = (c.w >> 1) - ix;
                        const bool vz = zo || (iz ? (c.y > 0) : (mz < DM));
                        const bool vy = yo || (iy ? (c.z > 0) : (my < HM));
                        const bool vx = xo || (ix ? (c.w > 0) : (mx < WM));
                        if (vz && vy && vx) {
                            float* p = g_mid + ((((c.x * DM + mz) * HM + my) * WM + mx) << 6) + 4 * q;
                            const uint2 a0 = *reinterpret_cast<const uint2*>(&acc[i][0]);
                            const uint2 a1 = *reinterpret_cast<const uint2*>(&acc[i][1]);
                            // NOTE: no "memory" clobber — red has no intra-kernel
                            // ordering requirement (g_mid never read here); lets
                            // ptxas pipeline next tap's smem loads across atomics.
                            asm volatile("red.global.add.v4.f32 [%0], {%1,%2,%3,%4};"
                                :: "l"(p),
                                   "f"(__uint_as_float(a0.x)), "f"(__uint_as_float(a0.y)),
                                   "f"(__uint_as_float(a1.x)), "f"(__uint_as_float(a1.y)));
                        }
                    }
                }
            }
        }
    }
}

// ---------------------------------------------------------------------------
// Phase 3: gather transposed-conv. lane = ci. Software-pipelined: tap it+1's
// mid rows are prefetched (float2 LDG, registers) while tap it's FMA runs.
// Weights transposed in smem: [tap][cog][ci] float4.
// ---------------------------------------------------------------------------
__global__ void __launch_bounds__(32 * NWG, 2) gather_deconv(
    const int*   __restrict__ coors,
    const float* __restrict__ w2,
    float*       __restrict__ out) {
    extern __shared__ float sh[];
    float4* ws4 = reinterpret_cast<float4*>(sh);        // [it][cog][ci] float4
    float*  mst = sh + 16384;                           // NWG * GP*64 floats
    int4* sco = reinterpret_cast<int4*>(mst + NWG * GP * 64);
    __shared__ int s_chunk;

    const int tid  = threadIdx.x;
    const int warp = tid >> 5, lane = tid & 31;
    float* msw = mst + warp * (GP * 64);
    const float4* msw4 = reinterpret_cast<const float4*>(msw);
    int4* scow = sco + warp * GP;
    const int4* c4 = reinterpret_cast<const int4*>(coors);
    const float4* w2_4 = reinterpret_cast<const float4*>(w2);
    const float2* mid2 = reinterpret_cast<const float2*>(g_mid);

    int loaded = -1;
    for (int b = 0; b < 8; b++) {
        const int zo = (b >> 2) & 1, yo = (b >> 1) & 1, xo = b & 1;
        const int nx = 2 - xo, ny = 2 - yo, nz = 2 - zo;
        const int ntap = nx * ny * nz;
        const int ng = g_ng[b];
        const int bs = g_bstart[b], bc = g_cntS[b];
        while (true) {
            __syncthreads();
            if (tid == 0) s_chunk = atomicAdd(&g_ccur2[b], NWG);
            __syncthreads();
            const int ch = s_chunk;
            if (ch >= ng) break;
            if (loaded != b) {
                for (int i = tid; i < ntap * 512; i += blockDim.x) {
                    const int it = i >> 9, cog = (i >> 5) & 15, ci = i & 31;
                    const int ix = it % nx, iy = (it / nx) % ny, iz = it / (nx * ny);
                    const int kz = zo ? 1 : (iz ? 2 : 0);
                    const int ky = yo ? 1 : (iy ? 2 : 0);
                    const int kx = xo ? 1 : (ix ? 2 : 0);
                    ws4[i] = w2_4[(((kz * 3 + ky) * 3 + kx) * 32 + ci) * 16 + cog];
                }
                __syncthreads();
                loaded = b;
            }
            const int gi = ch + warp;
            if (gi >= ng) continue;
            const int base = bs + gi * GP;
            const int cnt  = min(GP, bs + bc - base);

            int4 cj = make_int4(0, 0, 0, 0);
            if (lane < GP) {
                const int id = g_order[base + ((lane < cnt) ? lane : 0)];
                cj = __ldg(c4 + id);
                scow[lane] = cj;
            }
            __syncwarp();

            // per-lane mid row base for tap `it` of this lane's point (-1 invalid)
            auto mb_of = [&](int it) -> int {
                if (lane >= cnt) return -1;
                const int ix = it % nx, iy = (it / nx) % ny, iz = it / (nx * ny);
                const int mz = (cj.y >> 1) - iz;
                const int my = (cj.z >> 1) - iy;
                const int mx = (cj.w >> 1) - ix;
                const bool vz = zo || (iz ? (cj.y > 0) : (mz < DM));
                const bool vy = yo || (iy ? (cj.z > 0) : (my < HM));
                const bool vx = xo || (ix ? (cj.w > 0) : (mx < WM));
                return (vz && vy && vx) ? ((((cj.x * DM + mz) * HM + my) * WM + mx) << 6) : -1;
            };
            // prefetch rows for tap `it` into regs (8 x LDG.64 coalesced)
            float2 pf[GP];
            auto fetch_tap = [&](int it, float2* buf) {
                const int mbj = mb_of(it);
                #pragma unroll
                for (int j = 0; j < GP; j++) {
                    const int mb = __shfl_sync(0xffffffffu, mbj, j);
                    buf[j] = (mb >= 0) ? __ldg(mid2 + (mb >> 1) + lane)
                                       : make_float2(0.f, 0.f);
                }
            };

            fetch_tap(0, pf);
            unsigned long long acc[GP] = {0, 0, 0, 0, 0, 0, 0, 0};
            for (int it = 0; it < ntap; it++) {
                __syncwarp();   // previous FMA done before overwriting msw
                #pragma unroll
                for (int j = 0; j < GP; j++)
                    *reinterpret_cast<float2*>(msw + j * 64 + 2 * lane) = pf[j];
                if (it + 1 < ntap) fetch_tap(it + 1, pf);  // LDGs fly during FMA
                __syncwarp();

                const float4* wt = ws4 + it * 512;
                #pragma unroll
                for (int cog = 0; cog < 16; cog++) {
                    const ulonglong2 w = *reinterpret_cast<const ulonglong2*>(wt + cog * 32 + lane);
                    #pragma unroll
                    for (int j = 0; j < GP; j++) {
                        const ulonglong2 m = *reinterpret_cast<const ulonglong2*>(msw4 + j * 16 + cog);
                        ffma2(acc[j], m.x, w.x);
                        ffma2(acc[j], m.y, w.y);
                    }
                }
            }

            for (int j = 0; j < cnt; j++) {
                const int4 c = scow[j];
                const uint2 a = *reinterpret_cast<const uint2*>(&acc[j]);
                const float r = __uint_as_float(a.x) + __uint_as_float(a.y);
                long o = (long)(c.x * CIN + lane) * DD + c.y;
                o = o * HH + c.z;
                o = o * WW + c.w;
                out[o] = r;
            }
        }
    }
}

// ---------------------------------------------------------------------------
// Launcher
// ---------------------------------------------------------------------------
extern "C" void kernel_launch(void* const* d_in, const int* in_sizes, int n_in,
                              void* d_out, int /*out_size*/) {
    const float* feats = nullptr;
    const int*   coors = nullptr;
    const float* w1 = nullptr;
    const float* w2 = nullptr;
    for (int i = 0; i < n_in; i++) {
        if      (in_sizes[i] == NPTS * CIN) feats = (const float*)d_in[i];
        else if (in_sizes[i] == NPTS * 4)   coors = (const int*)d_in[i];
        else if (in_sizes[i] == WSZ) {
            if (!w1) w1 = (const float*)d_in[i];
            else     w2 = (const float*)d_in[i];
        }
    }
    if (!feats || !coors || !w1 || !w2) return;

    int nsm = 148;
    cudaDeviceGetAttribute(&nsm, cudaDevAttrMultiProcessorCount, 0);

    const int smem1 = 16384 * 4 + NW * GP * 32 * 8 + NW * GP * 16;        // 100,352 B
    const int smem3 = 16384 * 4 + NWG * GP * 64 * 4 + NWG * GP * 16;      //  91,648 B
    cudaFuncSetAttribute(scatter_conv,  cudaFuncAttributeMaxDynamicSharedMemorySize, smem1);
    cudaFuncSetAttribute(gather_deconv, cudaFuncAttributeMaxDynamicSharedMemorySize, smem3);

    zero_hist<<<2048, 256>>>(reinterpret_cast<float4*>(d_out), coors);
    scan_kernel<<<1, 1>>>();
    scatter_idx_kernel<<<(NPTS + 255) / 256, 256>>>(coors);
    scatter_conv<<<2 * nsm, 512, smem1>>>(feats, coors, w1);
    gather_deconv<<<2 * nsm, 32 * NWG, smem3>>>(coors, w2, reinterpret_cast<float*>(d_out));
}